// round 2
// baseline (speedup 1.0000x reference)
#include <cuda_runtime.h>
#include <cuda_bf16.h>
#include <math_constants.h>

#define DIM 4096
#define CAP 8192
#define VEC (DIM / 4)      // 1024 float4 per row
#define MAXK 64

// Scratch (no allocations allowed)
__device__ float g_scores[CAP];
__device__ float g_retrieved[DIM];

// ---------------------------------------------------------------------------
// Block-wide 3-value sum reduction helper (warp shuffle + smem)
// ---------------------------------------------------------------------------
__device__ __forceinline__ void block_reduce3(float& a, float& b, float& c) {
    __shared__ float sa[8], sb[8], sc[8];
    int lane = threadIdx.x & 31;
    int wid  = threadIdx.x >> 5;
    #pragma unroll
    for (int off = 16; off > 0; off >>= 1) {
        a += __shfl_down_sync(0xffffffffu, a, off);
        b += __shfl_down_sync(0xffffffffu, b, off);
        c += __shfl_down_sync(0xffffffffu, c, off);
    }
    if (lane == 0) { sa[wid] = a; sb[wid] = b; sc[wid] = c; }
    __syncthreads();
    if (wid == 0) {
        int nw = blockDim.x >> 5;
        a = (lane < nw) ? sa[lane] : 0.0f;
        b = (lane < nw) ? sb[lane] : 0.0f;
        c = (lane < nw) ? sc[lane] : 0.0f;
        #pragma unroll
        for (int off = 4; off > 0; off >>= 1) {
            a += __shfl_down_sync(0xffffffffu, a, off);
            b += __shfl_down_sync(0xffffffffu, b, off);
            c += __shfl_down_sync(0xffffffffu, c, off);
        }
    }
}

// ---------------------------------------------------------------------------
// Kernel 1: weighted cosine-similarity scores. One block per memory row.
// Reads 128 MB of memory_bank -> DRAM bound.
// ---------------------------------------------------------------------------
__global__ void __launch_bounds__(256, 8)
scores_kernel(const float* __restrict__ query,
              const float* __restrict__ memory_bank,
              const float* __restrict__ importance,
              const float* __restrict__ age) {
    int row = blockIdx.x;
    const float4* q4 = reinterpret_cast<const float4*>(query);
    const float4* m4 = reinterpret_cast<const float4*>(memory_bank + (size_t)row * DIM);

    float dot = 0.0f, msq = 0.0f, qsq = 0.0f;
    #pragma unroll 4
    for (int i = threadIdx.x; i < VEC; i += 256) {
        float4 q = q4[i];
        float4 m = m4[i];
        dot += q.x * m.x + q.y * m.y + q.z * m.z + q.w * m.w;
        msq += m.x * m.x + m.y * m.y + m.z * m.z + m.w * m.w;
        qsq += q.x * q.x + q.y * q.y + q.z * q.z + q.w * q.w;
    }
    block_reduce3(dot, msq, qsq);
    if (threadIdx.x == 0) {
        float denom = fmaxf(sqrtf(qsq) * sqrtf(msq), 1e-8f);
        float sim = dot / denom;
        g_scores[row] = sim * importance[row] * expf(-0.001f * age[row]);
    }
}

// ---------------------------------------------------------------------------
// Kernel 2: top-k (jax tie-break: smaller index wins on equal value) + mean
// pool of selected rows into g_retrieved. Single block.
// ---------------------------------------------------------------------------
__global__ void __launch_bounds__(256, 1)
topk_mean_kernel(const float* __restrict__ memory_bank,
                 const int* __restrict__ top_k_ptr) {
    __shared__ float s[CAP];           // 32 KB
    __shared__ float rv[256];
    __shared__ int   ri[256];
    __shared__ int   chosen[MAXK];

    int tid = threadIdx.x;
    for (int i = tid; i < CAP; i += 256) s[i] = g_scores[i];
    __syncthreads();

    int k = top_k_ptr[0];
    if (k < 1) k = 1;
    if (k > MAXK) k = MAXK;

    for (int r = 0; r < k; r++) {
        float best = -CUDART_INF_F;
        int   bi   = CAP;
        // ascending stride scan: strict '>' keeps the smallest index on ties
        for (int i = tid; i < CAP; i += 256) {
            float v = s[i];
            if (v > best) { best = v; bi = i; }
        }
        rv[tid] = best; ri[tid] = bi;
        __syncthreads();
        for (int off = 128; off > 0; off >>= 1) {
            if (tid < off) {
                float ov = rv[tid + off]; int oi = ri[tid + off];
                if (ov > rv[tid] || (ov == rv[tid] && oi < ri[tid])) {
                    rv[tid] = ov; ri[tid] = oi;
                }
            }
            __syncthreads();
        }
        if (tid == 0) {
            chosen[r] = ri[0];
            s[ri[0]] = -CUDART_INF_F;
        }
        __syncthreads();
    }

    // mean-pool the k selected rows -> g_retrieved
    float invk = 1.0f / (float)k;
    for (int j = tid; j < VEC; j += 256) {
        float4 acc = make_float4(0.f, 0.f, 0.f, 0.f);
        for (int r = 0; r < k; r++) {
            const float4* row4 =
                reinterpret_cast<const float4*>(memory_bank + (size_t)chosen[r] * DIM);
            float4 v = row4[j];
            acc.x += v.x; acc.y += v.y; acc.z += v.z; acc.w += v.w;
        }
        reinterpret_cast<float4*>(g_retrieved)[j] =
            make_float4(acc.x * invk, acc.y * invk, acc.z * invk, acc.w * invk);
    }
}

// ---------------------------------------------------------------------------
// Kernel 3: out[i] = b[i] + sum_j W[i][j] * retrieved[j]. One block per out
// element. Reads 64 MB of W_dec -> DRAM bound.
// ---------------------------------------------------------------------------
__global__ void __launch_bounds__(256, 8)
decode_kernel(const float* __restrict__ W_dec,
              const float* __restrict__ b_dec,
              float* __restrict__ out) {
    int row = blockIdx.x;
    const float4* w4 = reinterpret_cast<const float4*>(W_dec + (size_t)row * DIM);
    const float4* r4 = reinterpret_cast<const float4*>(g_retrieved);

    float acc = 0.0f, d1 = 0.0f, d2 = 0.0f;
    #pragma unroll 4
    for (int i = threadIdx.x; i < VEC; i += 256) {
        float4 w = w4[i];
        float4 r = r4[i];
        acc += w.x * r.x + w.y * r.y + w.z * r.z + w.w * r.w;
    }
    block_reduce3(acc, d1, d2);
    if (threadIdx.x == 0) out[row] = acc + b_dec[row];
}

// ---------------------------------------------------------------------------
extern "C" void kernel_launch(void* const* d_in, const int* in_sizes, int n_in,
                              void* d_out, int out_size) {
    const float* query       = (const float*)d_in[0];
    const float* memory_bank = (const float*)d_in[1];
    const float* importance  = (const float*)d_in[2];
    const float* age         = (const float*)d_in[3];
    const float* W_dec       = (const float*)d_in[4];
    const float* b_dec       = (const float*)d_in[5];
    const int*   top_k       = (const int*)d_in[6];
    float* out = (float*)d_out;

    scores_kernel<<<CAP, 256>>>(query, memory_bank, importance, age);
    topk_mean_kernel<<<1, 256>>>(memory_bank, top_k);
    decode_kernel<<<DIM, 256>>>(W_dec, b_dec, out);
}